// round 16
// baseline (speedup 1.0000x reference)
#include <cuda_runtime.h>
#include <cuda_fp16.h>
#include <math.h>
#include <stdint.h>

#define SEQ     4096
#define DMODEL  2048
#define DHEAD   128
#define NH      16
#define NKV     4
#define NCOLS   3072
#define KDIM    2048

// ---------------- scratch ----------------
__device__ __align__(256) float g_bcat[NCOLS];
__device__ __align__(256) __half g_xh[SEQ * DMODEL];       // x fp16
__device__ __align__(256) __half g_zh[SEQ * DMODEL];       // z fp16
__device__ __align__(256) __half g_Wthi[NCOLS * KDIM];     // QKV W^T fp16
__device__ __align__(256) __half g_WOthi[DMODEL * KDIM];   // W_O^T fp16
__device__ __align__(256) __half g_qh[SEQ * DMODEL];       // Q fp16 (post-rotary)
__device__ __align__(256) __half g_kh[NKV * SEQ * DHEAD];  // K fp16 (post-rotary)
__device__ __align__(256) __half g_vthi[NKV * DHEAD * SEQ];// V^T fp16
__device__ __align__(256) float g_rcos[SEQ * 64];
__device__ __align__(256) float g_rsin[SEQ * 64];

// ---------------- helpers ----------------
__device__ __forceinline__ uint32_t smem_u32(const void* p) {
    uint32_t a;
    asm("{ .reg .u64 t; cvta.to.shared.u64 t, %1; cvt.u32.u64 %0, t; }" : "=r"(a) : "l"(p));
    return a;
}
__device__ __forceinline__ void cp16(uint32_t s, const void* g) {
    asm volatile("cp.async.cg.shared.global [%0], [%1], 16;" :: "r"(s), "l"(g));
}
#define CP_COMMIT() asm volatile("cp.async.commit_group;" ::: "memory")
__device__ __forceinline__ void ldsm4(uint32_t* r, uint32_t addr) {
    asm volatile("ldmatrix.sync.aligned.m8n8.x4.shared.b16 {%0,%1,%2,%3}, [%4];"
        : "=r"(r[0]), "=r"(r[1]), "=r"(r[2]), "=r"(r[3]) : "r"(addr));
}
__device__ __forceinline__ void mma_f16(float* d, const uint32_t* a, const uint32_t* b) {
    asm volatile("mma.sync.aligned.m16n8k16.row.col.f32.f16.f16.f32 "
        "{%0,%1,%2,%3}, {%4,%5,%6,%7}, {%8,%9}, {%0,%1,%2,%3};"
        : "+f"(d[0]), "+f"(d[1]), "+f"(d[2]), "+f"(d[3])
        : "r"(a[0]), "r"(a[1]), "r"(a[2]), "r"(a[3]), "r"(b[0]), "r"(b[1]));
}
__device__ __forceinline__ float ex2f(float x) {
    float y; asm("ex2.approx.ftz.f32 %0, %1;" : "=f"(y) : "f"(x)); return y;
}
__device__ __forceinline__ uint32_t f16x2(float p0, float p1) {
    uint32_t r;
    asm("cvt.rn.f16x2.f32 %0, %1, %2;" : "=r"(r) : "f"(p1), "f"(p0));
    return r;
}
__device__ __forceinline__ void store1h(__half* dst, size_t off, float v0, float v1) {
    *(__half2*)(dst + off) = __half2(__float2half_rn(v0), __float2half_rn(v1));
}
#define SWZ(off) ((off) ^ (((off) >> 3) & 0x70))

// ---------------- mono prep kernel (unchanged from R12) ----------------
#define PB_QKV   6144
#define PB_ROT   (PB_QKV + 1024)
#define PB_BIAS  (PB_ROT + 12)
#define PB_WO    (PB_BIAS + 4096)
#define PB_CONV  (PB_WO + 4096)
__global__ void prep_all(const float* __restrict__ x,
                         const float* __restrict__ WQ, const float* __restrict__ WK,
                         const float* __restrict__ WV, const float* __restrict__ WO,
                         const float* __restrict__ bQ, const float* __restrict__ bK,
                         const float* __restrict__ bV) {
    int b = blockIdx.x;
    int tid = threadIdx.x;
    if (b < PB_QKV) {
        __shared__ float tile[32][33];
        int H = b >> 8;
        int rem = b & 255;
        int k0 = (rem >> 2) * 32;
        int h0 = (rem & 3) * 32;
        const float* src;
        int nbase;
        if (H < 16)      { src = WQ + (size_t)H * KDIM * DHEAD;        nbase = H * 128; }
        else if (H < 20) { src = WK + (size_t)(H - 16) * KDIM * DHEAD; nbase = 2048 + (H - 16) * 128; }
        else             { src = WV + (size_t)(H - 20) * KDIM * DHEAD; nbase = 2560 + (H - 20) * 128; }
        int c = tid & 31, r0t = tid >> 5;
        #pragma unroll
        for (int p = 0; p < 4; p++) {
            int r = r0t + p * 8;
            tile[r][c] = src[(size_t)(k0 + r) * DHEAD + h0 + c];
        }
        __syncthreads();
        #pragma unroll
        for (int p = 0; p < 4; p++) {
            int rr = r0t + p * 8;
            g_Wthi[(size_t)(nbase + h0 + rr) * KDIM + k0 + c] = __float2half_rn(tile[c][rr]);
        }
        return;
    }
    if (b < PB_ROT) {
        int idx = (b - PB_QKV) * 256 + tid;
        int j = idx & 63, s = idx >> 6;
        double dfreq = pow(10000.0, -(double)j / 64.0);
        float freq = (float)dfreq;
        float angle = (float)s * freq;
        double da = (double)angle;
        g_rcos[idx] = (float)cos(da);
        g_rsin[idx] = (float)sin(da);
        return;
    }
    if (b < PB_BIAS) {
        int idx = (b - PB_ROT) * 256 + tid;
        if (idx >= NCOLS) return;
        float v;
        if      (idx < 2048) v = bQ[idx];
        else if (idx < 2560) v = bK[idx - 2048];
        else                 v = bV[idx - 2560];
        g_bcat[idx] = v;
        return;
    }
    if (b < PB_WO) {
        __shared__ float tile[32][33];
        int i = b - PB_BIAS;
        int n0 = (i >> 6) * 32;
        int m0 = (i & 63) * 32;
        int c = tid & 31, r0t = tid >> 5;
        #pragma unroll
        for (int p = 0; p < 4; p++) {
            int r = r0t + p * 8;
            tile[r][c] = WO[(size_t)(n0 + r) * DMODEL + m0 + c];
        }
        __syncthreads();
        #pragma unroll
        for (int p = 0; p < 4; p++) {
            int rr = r0t + p * 8;
            g_WOthi[(size_t)(m0 + rr) * KDIM + n0 + c] = __float2half_rn(tile[c][rr]);
        }
        return;
    }
    {
        int base = (b - PB_WO) * 2048 + tid * 8;
        float4 v0 = *(const float4*)(x + base);
        float4 v1 = *(const float4*)(x + base + 4);
        __half h[8];
        h[0] = __float2half_rn(v0.x); h[1] = __float2half_rn(v0.y);
        h[2] = __float2half_rn(v0.z); h[3] = __float2half_rn(v0.w);
        h[4] = __float2half_rn(v1.x); h[5] = __float2half_rn(v1.y);
        h[6] = __float2half_rn(v1.z); h[7] = __float2half_rn(v1.w);
        *(uint4*)(g_xh + base) = *(uint4*)h;
    }
}

// ---------------- persistent fp16 GEMM: BM=128, BN=256, warp 64x64, BKT=128 ----------------
// smem per stage: A 2 planes x 16KB + B 2 planes x 32KB = 96KB; double buffered = 192KB.
#define BM 128
#define BN 256
#define BKT 128
#define APL 16384              // A plane: 128 rows x 128B
#define BPL 32768              // B plane: 256 rows x 128B
#define SMB_OFF (2 * APL)      // B region offset within buffer
#define BUFB (2 * APL + 2 * BPL)   // 96 KB
#define GSMEM (2 * BUFB)           // 192 KB
#define NSTG (KDIM / BKT)          // 16

__device__ __forceinline__ void load_stage(uint32_t bb, int k0, int m0, int n0, int tid,
                                           const __half* Ah, const __half* Bh) {
    // A: 2048 16B-chunks (2 planes x 128 rows x 8 chunks)
    #pragma unroll
    for (int i = 0; i < 8; i++) {
        int c = tid + i * 256;
        int pl = c >> 10, r = (c & 1023) >> 3, ch = c & 7;
        cp16(bb + pl * APL + SWZ(r * 128 + ch * 16),
             Ah + (size_t)(m0 + r) * KDIM + k0 + pl * 64 + ch * 8);
    }
    // B: 4096 chunks (2 planes x 256 rows x 8 chunks)
    #pragma unroll
    for (int i = 0; i < 16; i++) {
        int c = tid + i * 256;
        int pl = c >> 11, r = (c & 2047) >> 3, ch = c & 7;
        cp16(bb + SMB_OFF + pl * BPL + SWZ(r * 128 + ch * 16),
             Bh + (size_t)(n0 + r) * KDIM + k0 + pl * 64 + ch * 8);
    }
}

template<int EPI>
__global__ __launch_bounds__(256, 1) void gemm3(
    const __half* __restrict__ Ah, const __half* __restrict__ Bh,
    const float* __restrict__ bias, float* __restrict__ C, int N,
    int ntm, int ntiles)
{
    extern __shared__ char sm[];
    const uint32_t smb = smem_u32(sm);
    const int tid = threadIdx.x;
    const int wid = tid >> 5, lid = tid & 31;
    const int wm = (wid & 1) * 64;
    const int wn = (wid >> 1) * 64;

    const int arow = lid & 15;
    const int asel = (lid >> 4) * 16;
    const int brow = ((lid >> 4) << 3) + (lid & 7);
    const int bsel = ((lid >> 3) & 1) * 16;

    for (int tile = blockIdx.x; tile < ntiles; tile += gridDim.x) {
        const int m0 = (tile % ntm) * BM;
        const int n0 = (tile / ntm) * BN;

        float acc[4][8][4];
        #pragma unroll
        for (int i = 0; i < 4; i++)
            #pragma unroll
            for (int j = 0; j < 8; j++)
                #pragma unroll
                for (int k = 0; k < 4; k++) acc[i][j][k] = 0.f;

        load_stage(smb, 0, m0, n0, tid, Ah, Bh);
        CP_COMMIT();

        for (int s = 0; s < NSTG; s++) {
            if (s + 1 < NSTG) {
                load_stage(smb + ((s + 1) & 1) * BUFB, (s + 1) * BKT, m0, n0, tid, Ah, Bh);
                CP_COMMIT();
                asm volatile("cp.async.wait_group 1;" ::: "memory");
            } else {
                asm volatile("cp.async.wait_group 0;" ::: "memory");
            }
            __syncthreads();

            uint32_t bb = smb + (s & 1) * BUFB;
            #pragma unroll
            for (int kk = 0; kk < 8; kk++) {
                int pl = kk >> 2, koff = (kk & 3) * 32;
                uint32_t ah[4][4];
                #pragma unroll
                for (int ms = 0; ms < 4; ms++)
                    ldsm4(ah[ms], bb + pl * APL + SWZ((wm + ms * 16 + arow) * 128 + koff + asel));
                uint32_t bh[4][4];
                #pragma unroll
                for (int ns = 0; ns < 4; ns++)
                    ldsm4(bh[ns], bb + SMB_OFF + pl * BPL + SWZ((wn + ns * 16 + brow) * 128 + koff + bsel));
                #pragma unroll
                for (int ms = 0; ms < 4; ms++)
                    #pragma unroll
                    for (int n8 = 0; n8 < 8; n8++)
                        mma_f16(acc[ms][n8], ah[ms], &bh[n8 >> 1][(n8 & 1) * 2]);
            }
            __syncthreads();
        }

        const int erow = lid >> 2, ecol = (lid & 3) * 2;
        #pragma unroll
        for (int ms = 0; ms < 4; ms++) {
            int r0 = m0 + wm + ms * 16 + erow;
            #pragma unroll
            for (int n8 = 0; n8 < 8; n8++) {
                int c = n0 + wn + n8 * 8 + ecol;
                float2 bv = *(const float2*)&bias[c];
                float a00 = acc[ms][n8][0] + bv.x, a01 = acc[ms][n8][1] + bv.y;
                float a10 = acc[ms][n8][2] + bv.x, a11 = acc[ms][n8][3] + bv.y;
                if (EPI == 0) {
                    *(float2*)&C[(size_t)r0 * N + c]       = make_float2(a00, a01);
                    *(float2*)&C[(size_t)(r0 + 8) * N + c] = make_float2(a10, a11);
                } else {
                    if (c < 2048) {                        // Q: rotary + fp16
                        int j = (c & 127) >> 1;
                        float c0 = g_rcos[r0 * 64 + j],       s0 = g_rsin[r0 * 64 + j];
                        float c1 = g_rcos[(r0 + 8) * 64 + j], s1 = g_rsin[(r0 + 8) * 64 + j];
                        store1h(g_qh, (size_t)r0 * DMODEL + c,
                                a00 * c0 - a01 * s0, a00 * s0 + a01 * c0);
                        store1h(g_qh, (size_t)(r0 + 8) * DMODEL + c,
                                a10 * c1 - a11 * s1, a10 * s1 + a11 * c1);
                    } else if (c < 2560) {                 // K: rotary + fp16, [kvh][s][dh]
                        int kvh = (c - 2048) >> 7, dh = c & 127, j = dh >> 1;
                        float c0 = g_rcos[r0 * 64 + j],       s0 = g_rsin[r0 * 64 + j];
                        float c1 = g_rcos[(r0 + 8) * 64 + j], s1 = g_rsin[(r0 + 8) * 64 + j];
                        size_t base = ((size_t)kvh * SEQ + r0) * DHEAD + dh;
                        store1h(g_kh, base,
                                a00 * c0 - a01 * s0, a00 * s0 + a01 * c0);
                        store1h(g_kh, base + 8 * DHEAD,
                                a10 * c1 - a11 * s1, a10 * s1 + a11 * c1);
                    } else {                               // V: fp16 + transpose [kvh][dh][s]
                        int kvh = (c - 2560) >> 7, dh = c & 127;
                        size_t b0 = ((size_t)kvh * DHEAD + dh) * SEQ;
                        size_t b1 = b0 + SEQ;
                        g_vthi[b0 + r0]     = __float2half_rn(a00);
                        g_vthi[b1 + r0]     = __float2half_rn(a01);
                        g_vthi[b0 + r0 + 8] = __float2half_rn(a10);
                        g_vthi[b1 + r0 + 8] = __float2half_rn(a11);
                    }
                }
            }
        }
        __syncthreads();   // protect smem reuse across tiles
    }
}

// ---------------- flash attention (fp16; BKV=128; 1 CTA/SM) — unchanged from R12 ----------------
#define SMK 32768
#define SMV 98304
#define ATT_SMEM 163840

__device__ __forceinline__ void load_kv_stage(uint32_t smb, int buf, int kv0, int tid,
                                              const __half* kh, const __half* vhi) {
    #pragma unroll
    for (int sb = 0; sb < 2; sb++) {
        #pragma unroll
        for (int i = 0; i < 4; i++) {
            int c = tid + i * 256;
            int r = c >> 3, ch = c & 7;
            cp16(smb + SMK + buf * 32768 + sb * 16384 + SWZ(r * 128 + ch * 16),
                 kh + (size_t)(kv0 + r) * DHEAD + sb * 64 + ch * 8);
        }
    }
    #pragma unroll
    for (int sb = 0; sb < 2; sb++) {
        #pragma unroll
        for (int i = 0; i < 4; i++) {
            int c = tid + i * 256;
            int d = c >> 3, ch = c & 7;
            cp16(smb + SMV + buf * 32768 + sb * 16384 + SWZ(d * 128 + ch * 16),
                 vhi + (size_t)d * SEQ + kv0 + sb * 64 + ch * 8);
        }
    }
}

__global__ __launch_bounds__(256, 1) void attn_mma() {
    extern __shared__ char sm[];
    const uint32_t smb = smem_u32(sm);
    const int tid = threadIdx.x;
    const int wid = tid >> 5, lid = tid & 31;
    const int qb = (int)(gridDim.x - 1) - (int)blockIdx.x;
    const int h = blockIdx.y;
    const int kvh = h >> 2;
    const int q0 = qb * 128;
    const int nkv = qb + 1;
    const int w16 = wid * 16;

    const int arow = lid & 15;
    const int asel = (lid >> 4) * 16;
    const int brow = ((lid >> 4) << 3) + (lid & 7);
    const int bsel = ((lid >> 3) & 1) * 16;

    const __half* kh  = g_kh + (size_t)kvh * SEQ * DHEAD;
    const __half* vhi = g_vthi + (size_t)kvh * DHEAD * SEQ;

    #pragma unroll
    for (int b = 0; b < 2; b++) {
        #pragma unroll
        for (int i = 0; i < 4; i++) {
            int c = tid + i * 256;
            int r = c >> 3, ch = c & 7;
            cp16(smb + b * 16384 + SWZ(r * 128 + ch * 16),
                 g_qh + (size_t)(q0 + r) * DMODEL + h * DHEAD + b * 64 + ch * 8);
        }
    }
    load_kv_stage(smb, 0, 0, tid, kh, vhi);
    CP_COMMIT();

    float oacc[16][4];
    #pragma unroll
    for (int i = 0; i < 16; i++)
        #pragma unroll
        for (int j = 0; j < 4; j++) oacc[i][j] = 0.f;
    float m2[2] = {-1e30f, -1e30f};
    float l2[2] = {0.f, 0.f};
    const float KE = (float)(1.4426950408889634 / 11.313708498984761);

    for (int kb = 0; kb < nkv; kb++) {
        if (kb + 1 < nkv) {
            load_kv_stage(smb, (kb + 1) & 1, (kb + 1) * 128, tid, kh, vhi);
            CP_COMMIT();
            asm volatile("cp.async.wait_group 1;" ::: "memory");
        } else {
            asm volatile("cp.async.wait_group 0;" ::: "memory");
        }
        __syncthreads();

        const uint32_t kbase = smb + SMK + (kb & 1) * 32768;
        const uint32_t vbase = smb + SMV + (kb & 1) * 32768;

        float sacc[16][4];
        #pragma unroll
        for (int i = 0; i < 16; i++)
            #pragma unroll
            for (int j = 0; j < 4; j++) sacc[i][j] = 0.f;

        #pragma unroll
        for (int kk = 0; kk < 8; kk++) {
            int sb = kk >> 2, koff = (kk & 3) * 32;
            uint32_t qh[4];
            ldsm4(qh, smb + sb * 16384 + SWZ((w16 + arow) * 128 + koff + asel));
            #pragma unroll
            for (int ns = 0; ns < 8; ns++) {
                uint32_t bk[4];
                ldsm4(bk, kbase + sb * 16384 + SWZ((ns * 16 + brow) * 128 + koff + bsel));
                mma_f16(sacc[2 * ns],     qh, bk);
                mma_f16(sacc[2 * ns + 1], qh, bk + 2);
            }
        }

        const int kv0 = kb * 128;
        const bool dodiag = (kb == nkv - 1);
        #pragma unroll
        for (int g = 0; g < 2; g++) {
            int grow = q0 + w16 + (lid >> 2) + g * 8;
            if (dodiag) {
                #pragma unroll
                for (int n8 = 0; n8 < 16; n8++) {
                    int col = kv0 + n8 * 8 + (lid & 3) * 2;
                    if (col > grow)     sacc[n8][2 * g]     = -1e30f;
                    if (col + 1 > grow) sacc[n8][2 * g + 1] = -1e30f;
                }
            }
            float mt = -1e30f;
            #pragma unroll
            for (int n8 = 0; n8 < 16; n8++)
                mt = fmaxf(mt, fmaxf(sacc[n8][2 * g], sacc[n8][2 * g + 1]));
            mt = fmaxf(mt, __shfl_xor_sync(0xffffffffu, mt, 1));
            mt = fmaxf(mt, __shfl_xor_sync(0xffffffffu, mt, 2));
            float mnew = fmaxf(m2[g], mt);
            float alpha = ex2f((m2[g] - mnew) * KE);
            float ls = 0.f;
            #pragma unroll
            for (int n8 = 0; n8 < 16; n8++) {
                float p0 = ex2f((sacc[n8][2 * g]     - mnew) * KE);
                float p1 = ex2f((sacc[n8][2 * g + 1] - mnew) * KE);
                sacc[n8][2 * g] = p0; sacc[n8][2 * g + 1] = p1;
                ls += p0 + p1;
            }
            ls += __shfl_xor_sync(0xffffffffu, ls, 1);
            ls += __shfl_xor_sync(0xffffffffu, ls, 2);
            l2[g] = l2[g] * alpha + ls;
            m2[g] = mnew;
            #pragma unroll
            for (int t = 0; t < 16; t++) {
                oacc[t][2 * g]     *= alpha;
                oacc[t][2 * g + 1] *= alpha;
            }
        }

        #pragma unroll
        for (int t = 0; t < 8; t++) {
            uint32_t pa[4];
            pa[0] = f16x2(sacc[2 * t][0],     sacc[2 * t][1]);
            pa[1] = f16x2(sacc[2 * t][2],     sacc[2 * t][3]);
            pa[2] = f16x2(sacc[2 * t + 1][0], sacc[2 * t + 1][1]);
            pa[3] = f16x2(sacc[2 * t + 1][2], sacc[2 * t + 1][3]);
            int sb = t >> 2, koff = (t & 3) * 32;
            #pragma unroll
            for (int ns = 0; ns < 8; ns++) {
                uint32_t vh[4];
                ldsm4(vh, vbase + sb * 16384 + SWZ((ns * 16 + brow) * 128 + koff + bsel));
                mma_f16(oacc[2 * ns],     pa, vh);
                mma_f16(oacc[2 * ns + 1], pa, vh + 2);
            }
        }
        __syncthreads();
    }

    float inv0 = 1.f / l2[0], inv1 = 1.f / l2[1];
    int r0 = q0 + w16 + (lid >> 2);
    int cb = h * DHEAD + (lid & 3) * 2;
    #pragma unroll
    for (int n8 = 0; n8 < 16; n8++) {
        int col = cb + n8 * 8;
        store1h(g_zh, (size_t)r0 * DMODEL + col,
                oacc[n8][0] * inv0, oacc[n8][1] * inv0);
        store1h(g_zh, (size_t)(r0 + 8) * DMODEL + col,
                oacc[n8][2] * inv1, oacc[n8][3] * inv1);
    }
}

// ---------------- launcher ----------------
extern "C" void kernel_launch(void* const* d_in, const int* in_sizes, int n_in,
                              void* d_out, int out_size) {
    const float* x  = (const float*)d_in[0];
    const float* WQ = (const float*)d_in[1];
    const float* WK = (const float*)d_in[2];
    const float* WV = (const float*)d_in[3];
    const float* WO = (const float*)d_in[4];
    const float* bQ = (const float*)d_in[5];
    const float* bK = (const float*)d_in[6];
    const float* bV = (const float*)d_in[7];
    const float* bO = (const float*)d_in[8];
    float* out = (float*)d_out;

    float* bcat;
    __half *xh, *zh, *Wthi, *WOthi;
    cudaGetSymbolAddress((void**)&bcat,  g_bcat);
    cudaGetSymbolAddress((void**)&xh,    g_xh);
    cudaGetSymbolAddress((void**)&zh,    g_zh);
    cudaGetSymbolAddress((void**)&Wthi,  g_Wthi);
    cudaGetSymbolAddress((void**)&WOthi, g_WOthi);

    cudaFuncSetAttribute(gemm3<0>, cudaFuncAttributeMaxDynamicSharedMemorySize, GSMEM);
    cudaFuncSetAttribute(gemm3<1>, cudaFuncAttributeMaxDynamicSharedMemorySize, GSMEM);
    cudaFuncSetAttribute(attn_mma, cudaFuncAttributeMaxDynamicSharedMemorySize, ATT_SMEM);

    // 1) all prep in one launch
    prep_all<<<PB_CONV, 256>>>(x, WQ, WK, WV, WO, bQ, bK, bV);

    // 2) QKV projection (persistent) + fused bias/rotary/layout epilogue
    {
        int ntm = SEQ / BM, ntiles = ntm * (NCOLS / BN);   // 32 x 12 = 384
        gemm3<1><<<148, 256, GSMEM>>>(xh, Wthi, bcat, nullptr, NCOLS, ntm, ntiles);
    }
    // 3) causal flash attention -> zh
    {
        dim3 grid(SEQ / 128, NH);
        attn_mma<<<grid, 256, ATT_SMEM>>>();
    }
    // 4) O-projection (persistent)
    {
        int ntm = SEQ / BM, ntiles = ntm * (DMODEL / BN);  // 32 x 8 = 256
        gemm3<0><<<148, 256, GSMEM>>>(zh, WOthi, bO, out, DMODEL, ntm, ntiles);
    }
}

// round 17
// speedup vs baseline: 1.0015x; 1.0015x over previous
#include <cuda_runtime.h>
#include <cuda_fp16.h>
#include <math.h>
#include <stdint.h>

#define SEQ     4096
#define DMODEL  2048
#define DHEAD   128
#define NH      16
#define NKV     4
#define NCOLS   3072
#define KDIM    2048

// ---------------- scratch ----------------
__device__ __align__(256) float g_bcat[NCOLS];
__device__ __align__(256) __half g_xh[SEQ * DMODEL];       // x fp16
__device__ __align__(256) __half g_zh[SEQ * DMODEL];       // z fp16
__device__ __align__(256) __half g_Wthi[NCOLS * KDIM];     // QKV W^T fp16
__device__ __align__(256) __half g_WOthi[DMODEL * KDIM];   // W_O^T fp16
__device__ __align__(256) __half g_qh[SEQ * DMODEL];       // Q fp16 (post-rotary)
__device__ __align__(256) __half g_kh[NKV * SEQ * DHEAD];  // K fp16 (post-rotary)
__device__ __align__(256) __half g_vthi[NKV * DHEAD * SEQ];// V^T fp16
__device__ __align__(256) float g_rcos[SEQ * 64];
__device__ __align__(256) float g_rsin[SEQ * 64];

// ---------------- helpers ----------------
__device__ __forceinline__ uint32_t smem_u32(const void* p) {
    uint32_t a;
    asm("{ .reg .u64 t; cvta.to.shared.u64 t, %1; cvt.u32.u64 %0, t; }" : "=r"(a) : "l"(p));
    return a;
}
__device__ __forceinline__ void cp16(uint32_t s, const void* g) {
    asm volatile("cp.async.cg.shared.global [%0], [%1], 16;" :: "r"(s), "l"(g));
}
#define CP_COMMIT() asm volatile("cp.async.commit_group;" ::: "memory")
__device__ __forceinline__ void ldsm4(uint32_t* r, uint32_t addr) {
    asm volatile("ldmatrix.sync.aligned.m8n8.x4.shared.b16 {%0,%1,%2,%3}, [%4];"
        : "=r"(r[0]), "=r"(r[1]), "=r"(r[2]), "=r"(r[3]) : "r"(addr));
}
__device__ __forceinline__ void mma_f16(float* d, const uint32_t* a, const uint32_t* b) {
    asm volatile("mma.sync.aligned.m16n8k16.row.col.f32.f16.f16.f32 "
        "{%0,%1,%2,%3}, {%4,%5,%6,%7}, {%8,%9}, {%0,%1,%2,%3};"
        : "+f"(d[0]), "+f"(d[1]), "+f"(d[2]), "+f"(d[3])
        : "r"(a[0]), "r"(a[1]), "r"(a[2]), "r"(a[3]), "r"(b[0]), "r"(b[1]));
}
__device__ __forceinline__ float ex2f(float x) {
    float y; asm("ex2.approx.ftz.f32 %0, %1;" : "=f"(y) : "f"(x)); return y;
}
__device__ __forceinline__ uint32_t f16x2(float p0, float p1) {
    uint32_t r;
    asm("cvt.rn.f16x2.f32 %0, %1, %2;" : "=r"(r) : "f"(p1), "f"(p0));
    return r;
}
__device__ __forceinline__ void store1h(__half* dst, size_t off, float v0, float v1) {
    *(__half2*)(dst + off) = __half2(__float2half_rn(v0), __float2half_rn(v1));
}
#define SWZ(off) ((off) ^ (((off) >> 3) & 0x70))

// ---------------- mono prep kernel (unchanged from R12) ----------------
#define PB_QKV   6144
#define PB_ROT   (PB_QKV + 1024)
#define PB_BIAS  (PB_ROT + 12)
#define PB_WO    (PB_BIAS + 4096)
#define PB_CONV  (PB_WO + 4096)
__global__ void prep_all(const float* __restrict__ x,
                         const float* __restrict__ WQ, const float* __restrict__ WK,
                         const float* __restrict__ WV, const float* __restrict__ WO,
                         const float* __restrict__ bQ, const float* __restrict__ bK,
                         const float* __restrict__ bV) {
    int b = blockIdx.x;
    int tid = threadIdx.x;
    if (b < PB_QKV) {
        __shared__ float tile[32][33];
        int H = b >> 8;
        int rem = b & 255;
        int k0 = (rem >> 2) * 32;
        int h0 = (rem & 3) * 32;
        const float* src;
        int nbase;
        if (H < 16)      { src = WQ + (size_t)H * KDIM * DHEAD;        nbase = H * 128; }
        else if (H < 20) { src = WK + (size_t)(H - 16) * KDIM * DHEAD; nbase = 2048 + (H - 16) * 128; }
        else             { src = WV + (size_t)(H - 20) * KDIM * DHEAD; nbase = 2560 + (H - 20) * 128; }
        int c = tid & 31, r0t = tid >> 5;
        #pragma unroll
        for (int p = 0; p < 4; p++) {
            int r = r0t + p * 8;
            tile[r][c] = src[(size_t)(k0 + r) * DHEAD + h0 + c];
        }
        __syncthreads();
        #pragma unroll
        for (int p = 0; p < 4; p++) {
            int rr = r0t + p * 8;
            g_Wthi[(size_t)(nbase + h0 + rr) * KDIM + k0 + c] = __float2half_rn(tile[c][rr]);
        }
        return;
    }
    if (b < PB_ROT) {
        int idx = (b - PB_QKV) * 256 + tid;
        int j = idx & 63, s = idx >> 6;
        double dfreq = pow(10000.0, -(double)j / 64.0);
        float freq = (float)dfreq;
        float angle = (float)s * freq;
        double da = (double)angle;
        g_rcos[idx] = (float)cos(da);
        g_rsin[idx] = (float)sin(da);
        return;
    }
    if (b < PB_BIAS) {
        int idx = (b - PB_ROT) * 256 + tid;
        if (idx >= NCOLS) return;
        float v;
        if      (idx < 2048) v = bQ[idx];
        else if (idx < 2560) v = bK[idx - 2048];
        else                 v = bV[idx - 2560];
        g_bcat[idx] = v;
        return;
    }
    if (b < PB_WO) {
        __shared__ float tile[32][33];
        int i = b - PB_BIAS;
        int n0 = (i >> 6) * 32;
        int m0 = (i & 63) * 32;
        int c = tid & 31, r0t = tid >> 5;
        #pragma unroll
        for (int p = 0; p < 4; p++) {
            int r = r0t + p * 8;
            tile[r][c] = WO[(size_t)(n0 + r) * DMODEL + m0 + c];
        }
        __syncthreads();
        #pragma unroll
        for (int p = 0; p < 4; p++) {
            int rr = r0t + p * 8;
            g_WOthi[(size_t)(m0 + rr) * KDIM + n0 + c] = __float2half_rn(tile[c][rr]);
        }
        return;
    }
    {
        int base = (b - PB_WO) * 2048 + tid * 8;
        float4 v0 = *(const float4*)(x + base);
        float4 v1 = *(const float4*)(x + base + 4);
        __half h[8];
        h[0] = __float2half_rn(v0.x); h[1] = __float2half_rn(v0.y);
        h[2] = __float2half_rn(v0.z); h[3] = __float2half_rn(v0.w);
        h[4] = __float2half_rn(v1.x); h[5] = __float2half_rn(v1.y);
        h[6] = __float2half_rn(v1.z); h[7] = __float2half_rn(v1.w);
        *(uint4*)(g_xh + base) = *(uint4*)h;
    }
}

// ---------------- persistent fp16 GEMM: BM=128, BN=256, warp 64x64, BKT=128 ----------------
// smem per stage: A 2 planes x 16KB + B 2 planes x 32KB = 96KB; double buffered = 192KB.
#define BM 128
#define BN 256
#define BKT 128
#define APL 16384              // A plane: 128 rows x 128B
#define BPL 32768              // B plane: 256 rows x 128B
#define SMB_OFF (2 * APL)      // B region offset within buffer
#define BUFB (2 * APL + 2 * BPL)   // 96 KB
#define GSMEM (2 * BUFB)           // 192 KB
#define NSTG (KDIM / BKT)          // 16

__device__ __forceinline__ void load_stage(uint32_t bb, int k0, int m0, int n0, int tid,
                                           const __half* Ah, const __half* Bh) {
    // A: 2048 16B-chunks (2 planes x 128 rows x 8 chunks)
    #pragma unroll
    for (int i = 0; i < 8; i++) {
        int c = tid + i * 256;
        int pl = c >> 10, r = (c & 1023) >> 3, ch = c & 7;
        cp16(bb + pl * APL + SWZ(r * 128 + ch * 16),
             Ah + (size_t)(m0 + r) * KDIM + k0 + pl * 64 + ch * 8);
    }
    // B: 4096 chunks (2 planes x 256 rows x 8 chunks)
    #pragma unroll
    for (int i = 0; i < 16; i++) {
        int c = tid + i * 256;
        int pl = c >> 11, r = (c & 2047) >> 3, ch = c & 7;
        cp16(bb + SMB_OFF + pl * BPL + SWZ(r * 128 + ch * 16),
             Bh + (size_t)(n0 + r) * KDIM + k0 + pl * 64 + ch * 8);
    }
}

template<int EPI>
__global__ __launch_bounds__(256, 1) void gemm3(
    const __half* __restrict__ Ah, const __half* __restrict__ Bh,
    const float* __restrict__ bias, float* __restrict__ C, int N,
    int ntm, int ntiles)
{
    extern __shared__ char sm[];
    const uint32_t smb = smem_u32(sm);
    const int tid = threadIdx.x;
    const int wid = tid >> 5, lid = tid & 31;
    const int wm = (wid & 1) * 64;
    const int wn = (wid >> 1) * 64;

    const int arow = lid & 15;
    const int asel = (lid >> 4) * 16;
    const int brow = ((lid >> 4) << 3) + (lid & 7);
    const int bsel = ((lid >> 3) & 1) * 16;

    for (int tile = blockIdx.x; tile < ntiles; tile += gridDim.x) {
        const int m0 = (tile % ntm) * BM;
        const int n0 = (tile / ntm) * BN;

        float acc[4][8][4];
        #pragma unroll
        for (int i = 0; i < 4; i++)
            #pragma unroll
            for (int j = 0; j < 8; j++)
                #pragma unroll
                for (int k = 0; k < 4; k++) acc[i][j][k] = 0.f;

        load_stage(smb, 0, m0, n0, tid, Ah, Bh);
        CP_COMMIT();

        for (int s = 0; s < NSTG; s++) {
            if (s + 1 < NSTG) {
                load_stage(smb + ((s + 1) & 1) * BUFB, (s + 1) * BKT, m0, n0, tid, Ah, Bh);
                CP_COMMIT();
                asm volatile("cp.async.wait_group 1;" ::: "memory");
            } else {
                asm volatile("cp.async.wait_group 0;" ::: "memory");
            }
            __syncthreads();

            uint32_t bb = smb + (s & 1) * BUFB;
            #pragma unroll
            for (int kk = 0; kk < 8; kk++) {
                int pl = kk >> 2, koff = (kk & 3) * 32;
                uint32_t ah[4][4];
                #pragma unroll
                for (int ms = 0; ms < 4; ms++)
                    ldsm4(ah[ms], bb + pl * APL + SWZ((wm + ms * 16 + arow) * 128 + koff + asel));
                uint32_t bh[4][4];
                #pragma unroll
                for (int ns = 0; ns < 4; ns++)
                    ldsm4(bh[ns], bb + SMB_OFF + pl * BPL + SWZ((wn + ns * 16 + brow) * 128 + koff + bsel));
                #pragma unroll
                for (int ms = 0; ms < 4; ms++)
                    #pragma unroll
                    for (int n8 = 0; n8 < 8; n8++)
                        mma_f16(acc[ms][n8], ah[ms], &bh[n8 >> 1][(n8 & 1) * 2]);
            }
            __syncthreads();
        }

        const int erow = lid >> 2, ecol = (lid & 3) * 2;
        #pragma unroll
        for (int ms = 0; ms < 4; ms++) {
            int r0 = m0 + wm + ms * 16 + erow;
            #pragma unroll
            for (int n8 = 0; n8 < 8; n8++) {
                int c = n0 + wn + n8 * 8 + ecol;
                float2 bv = *(const float2*)&bias[c];
                float a00 = acc[ms][n8][0] + bv.x, a01 = acc[ms][n8][1] + bv.y;
                float a10 = acc[ms][n8][2] + bv.x, a11 = acc[ms][n8][3] + bv.y;
                if (EPI == 0) {
                    *(float2*)&C[(size_t)r0 * N + c]       = make_float2(a00, a01);
                    *(float2*)&C[(size_t)(r0 + 8) * N + c] = make_float2(a10, a11);
                } else {
                    if (c < 2048) {                        // Q: rotary + fp16
                        int j = (c & 127) >> 1;
                        float c0 = g_rcos[r0 * 64 + j],       s0 = g_rsin[r0 * 64 + j];
                        float c1 = g_rcos[(r0 + 8) * 64 + j], s1 = g_rsin[(r0 + 8) * 64 + j];
                        store1h(g_qh, (size_t)r0 * DMODEL + c,
                                a00 * c0 - a01 * s0, a00 * s0 + a01 * c0);
                        store1h(g_qh, (size_t)(r0 + 8) * DMODEL + c,
                                a10 * c1 - a11 * s1, a10 * s1 + a11 * c1);
                    } else if (c < 2560) {                 // K: rotary + fp16, [kvh][s][dh]
                        int kvh = (c - 2048) >> 7, dh = c & 127, j = dh >> 1;
                        float c0 = g_rcos[r0 * 64 + j],       s0 = g_rsin[r0 * 64 + j];
                        float c1 = g_rcos[(r0 + 8) * 64 + j], s1 = g_rsin[(r0 + 8) * 64 + j];
                        size_t base = ((size_t)kvh * SEQ + r0) * DHEAD + dh;
                        store1h(g_kh, base,
                                a00 * c0 - a01 * s0, a00 * s0 + a01 * c0);
                        store1h(g_kh, base + 8 * DHEAD,
                                a10 * c1 - a11 * s1, a10 * s1 + a11 * c1);
                    } else {                               // V: fp16 + transpose [kvh][dh][s]
                        int kvh = (c - 2560) >> 7, dh = c & 127;
                        size_t b0 = ((size_t)kvh * DHEAD + dh) * SEQ;
                        size_t b1 = b0 + SEQ;
                        g_vthi[b0 + r0]     = __float2half_rn(a00);
                        g_vthi[b1 + r0]     = __float2half_rn(a01);
                        g_vthi[b0 + r0 + 8] = __float2half_rn(a10);
                        g_vthi[b1 + r0 + 8] = __float2half_rn(a11);
                    }
                }
            }
        }
        __syncthreads();   // protect smem reuse across tiles
    }
}

// ---------------- flash attention (fp16; BKV=128; 1 CTA/SM) — unchanged from R12 ----------------
#define SMK 32768
#define SMV 98304
#define ATT_SMEM 163840

__device__ __forceinline__ void load_kv_stage(uint32_t smb, int buf, int kv0, int tid,
                                              const __half* kh, const __half* vhi) {
    #pragma unroll
    for (int sb = 0; sb < 2; sb++) {
        #pragma unroll
        for (int i = 0; i < 4; i++) {
            int c = tid + i * 256;
            int r = c >> 3, ch = c & 7;
            cp16(smb + SMK + buf * 32768 + sb * 16384 + SWZ(r * 128 + ch * 16),
                 kh + (size_t)(kv0 + r) * DHEAD + sb * 64 + ch * 8);
        }
    }
    #pragma unroll
    for (int sb = 0; sb < 2; sb++) {
        #pragma unroll
        for (int i = 0; i < 4; i++) {
            int c = tid + i * 256;
            int d = c >> 3, ch = c & 7;
            cp16(smb + SMV + buf * 32768 + sb * 16384 + SWZ(d * 128 + ch * 16),
                 vhi + (size_t)d * SEQ + kv0 + sb * 64 + ch * 8);
        }
    }
}

__global__ __launch_bounds__(256, 1) void attn_mma() {
    extern __shared__ char sm[];
    const uint32_t smb = smem_u32(sm);
    const int tid = threadIdx.x;
    const int wid = tid >> 5, lid = tid & 31;
    const int qb = (int)(gridDim.x - 1) - (int)blockIdx.x;
    const int h = blockIdx.y;
    const int kvh = h >> 2;
    const int q0 = qb * 128;
    const int nkv = qb + 1;
    const int w16 = wid * 16;

    const int arow = lid & 15;
    const int asel = (lid >> 4) * 16;
    const int brow = ((lid >> 4) << 3) + (lid & 7);
    const int bsel = ((lid >> 3) & 1) * 16;

    const __half* kh  = g_kh + (size_t)kvh * SEQ * DHEAD;
    const __half* vhi = g_vthi + (size_t)kvh * DHEAD * SEQ;

    #pragma unroll
    for (int b = 0; b < 2; b++) {
        #pragma unroll
        for (int i = 0; i < 4; i++) {
            int c = tid + i * 256;
            int r = c >> 3, ch = c & 7;
            cp16(smb + b * 16384 + SWZ(r * 128 + ch * 16),
                 g_qh + (size_t)(q0 + r) * DMODEL + h * DHEAD + b * 64 + ch * 8);
        }
    }
    load_kv_stage(smb, 0, 0, tid, kh, vhi);
    CP_COMMIT();

    float oacc[16][4];
    #pragma unroll
    for (int i = 0; i < 16; i++)
        #pragma unroll
        for (int j = 0; j < 4; j++) oacc[i][j] = 0.f;
    float m2[2] = {-1e30f, -1e30f};
    float l2[2] = {0.f, 0.f};
    const float KE = (float)(1.4426950408889634 / 11.313708498984761);

    for (int kb = 0; kb < nkv; kb++) {
        if (kb + 1 < nkv) {
            load_kv_stage(smb, (kb + 1) & 1, (kb + 1) * 128, tid, kh, vhi);
            CP_COMMIT();
            asm volatile("cp.async.wait_group 1;" ::: "memory");
        } else {
            asm volatile("cp.async.wait_group 0;" ::: "memory");
        }
        __syncthreads();

        const uint32_t kbase = smb + SMK + (kb & 1) * 32768;
        const uint32_t vbase = smb + SMV + (kb & 1) * 32768;

        float sacc[16][4];
        #pragma unroll
        for (int i = 0; i < 16; i++)
            #pragma unroll
            for (int j = 0; j < 4; j++) sacc[i][j] = 0.f;

        #pragma unroll
        for (int kk = 0; kk < 8; kk++) {
            int sb = kk >> 2, koff = (kk & 3) * 32;
            uint32_t qh[4];
            ldsm4(qh, smb + sb * 16384 + SWZ((w16 + arow) * 128 + koff + asel));
            #pragma unroll
            for (int ns = 0; ns < 8; ns++) {
                uint32_t bk[4];
                ldsm4(bk, kbase + sb * 16384 + SWZ((ns * 16 + brow) * 128 + koff + bsel));
                mma_f16(sacc[2 * ns],     qh, bk);
                mma_f16(sacc[2 * ns + 1], qh, bk + 2);
            }
        }

        const int kv0 = kb * 128;
        const bool dodiag = (kb == nkv - 1);
        #pragma unroll
        for (int g = 0; g < 2; g++) {
            int grow = q0 + w16 + (lid >> 2) + g * 8;
            if (dodiag) {
                #pragma unroll
                for (int n8 = 0; n8 < 16; n8++) {
                    int col = kv0 + n8 * 8 + (lid & 3) * 2;
                    if (col > grow)     sacc[n8][2 * g]     = -1e30f;
                    if (col + 1 > grow) sacc[n8][2 * g + 1] = -1e30f;
                }
            }
            float mt = -1e30f;
            #pragma unroll
            for (int n8 = 0; n8 < 16; n8++)
                mt = fmaxf(mt, fmaxf(sacc[n8][2 * g], sacc[n8][2 * g + 1]));
            mt = fmaxf(mt, __shfl_xor_sync(0xffffffffu, mt, 1));
            mt = fmaxf(mt, __shfl_xor_sync(0xffffffffu, mt, 2));
            float mnew = fmaxf(m2[g], mt);
            float alpha = ex2f((m2[g] - mnew) * KE);
            float ls = 0.f;
            #pragma unroll
            for (int n8 = 0; n8 < 16; n8++) {
                float p0 = ex2f((sacc[n8][2 * g]     - mnew) * KE);
                float p1 = ex2f((sacc[n8][2 * g + 1] - mnew) * KE);
                sacc[n8][2 * g] = p0; sacc[n8][2 * g + 1] = p1;
                ls += p0 + p1;
            }
            ls += __shfl_xor_sync(0xffffffffu, ls, 1);
            ls += __shfl_xor_sync(0xffffffffu, ls, 2);
            l2[g] = l2[g] * alpha + ls;
            m2[g] = mnew;
            #pragma unroll
            for (int t = 0; t < 16; t++) {
                oacc[t][2 * g]     *= alpha;
                oacc[t][2 * g + 1] *= alpha;
            }
        }

        #pragma unroll
        for (int t = 0; t < 8; t++) {
            uint32_t pa[4];
            pa[0] = f16x2(sacc[2 * t][0],     sacc[2 * t][1]);
            pa[1] = f16x2(sacc[2 * t][2],     sacc[2 * t][3]);
            pa[2] = f16x2(sacc[2 * t + 1][0], sacc[2 * t + 1][1]);
            pa[3] = f16x2(sacc[2 * t + 1][2], sacc[2 * t + 1][3]);
            int sb = t >> 2, koff = (t & 3) * 32;
            #pragma unroll
            for (int ns = 0; ns < 8; ns++) {
                uint32_t vh[4];
                ldsm4(vh, vbase + sb * 16384 + SWZ((ns * 16 + brow) * 128 + koff + bsel));
                mma_f16(oacc[2 * ns],     pa, vh);
                mma_f16(oacc[2 * ns + 1], pa, vh + 2);
            }
        }
        __syncthreads();
    }

    float inv0 = 1.f / l2[0], inv1 = 1.f / l2[1];
    int r0 = q0 + w16 + (lid >> 2);
    int cb = h * DHEAD + (lid & 3) * 2;
    #pragma unroll
    for (int n8 = 0; n8 < 16; n8++) {
        int col = cb + n8 * 8;
        store1h(g_zh, (size_t)r0 * DMODEL + col,
                oacc[n8][0] * inv0, oacc[n8][1] * inv0);
        store1h(g_zh, (size_t)(r0 + 8) * DMODEL + col,
                oacc[n8][2] * inv1, oacc[n8][3] * inv1);
    }
}

// ---------------- launcher ----------------
extern "C" void kernel_launch(void* const* d_in, const int* in_sizes, int n_in,
                              void* d_out, int out_size) {
    const float* x  = (const float*)d_in[0];
    const float* WQ = (const float*)d_in[1];
    const float* WK = (const float*)d_in[2];
    const float* WV = (const float*)d_in[3];
    const float* WO = (const float*)d_in[4];
    const float* bQ = (const float*)d_in[5];
    const float* bK = (const float*)d_in[6];
    const float* bV = (const float*)d_in[7];
    const float* bO = (const float*)d_in[8];
    float* out = (float*)d_out;

    float* bcat;
    __half *xh, *zh, *Wthi, *WOthi;
    cudaGetSymbolAddress((void**)&bcat,  g_bcat);
    cudaGetSymbolAddress((void**)&xh,    g_xh);
    cudaGetSymbolAddress((void**)&zh,    g_zh);
    cudaGetSymbolAddress((void**)&Wthi,  g_Wthi);
    cudaGetSymbolAddress((void**)&WOthi, g_WOthi);

    cudaFuncSetAttribute(gemm3<0>, cudaFuncAttributeMaxDynamicSharedMemorySize, GSMEM);
    cudaFuncSetAttribute(gemm3<1>, cudaFuncAttributeMaxDynamicSharedMemorySize, GSMEM);
    cudaFuncSetAttribute(attn_mma, cudaFuncAttributeMaxDynamicSharedMemorySize, ATT_SMEM);

    // 1) all prep in one launch
    prep_all<<<PB_CONV, 256>>>(x, WQ, WK, WV, WO, bQ, bK, bV);

    // 2) QKV projection (persistent) + fused bias/rotary/layout epilogue
    {
        int ntm = SEQ / BM, ntiles = ntm * (NCOLS / BN);   // 32 x 12 = 384
        gemm3<1><<<148, 256, GSMEM>>>(xh, Wthi, bcat, nullptr, NCOLS, ntm, ntiles);
    }
    // 3) causal flash attention -> zh
    {
        dim3 grid(SEQ / 128, NH);
        attn_mma<<<grid, 256, ATT_SMEM>>>();
    }
    // 4) O-projection (persistent)
    {
        int ntm = SEQ / BM, ntiles = ntm * (DMODEL / BN);  // 32 x 8 = 256
        gemm3<0><<<148, 256, GSMEM>>>(zh, WOthi, bO, out, DMODEL, ntm, ntiles);
    }
}